// round 16
// baseline (speedup 1.0000x reference)
#include <cuda_runtime.h>
#include <cuda_fp16.h>
#include <math.h>

#define FULL 0xffffffffu
#define B_ 8192
#define T_ 256
#define K_ 16
#define LOG2E 1.4426950408889634f
#define LN2   0.6931471805599453f

static __device__ __forceinline__ float ex2f_(float x){ float r; asm("ex2.approx.ftz.f32 %0,%1;":"=f"(r):"f"(x)); return r; }
static __device__ __forceinline__ float lg2f_(float x){ float r; asm("lg2.approx.ftz.f32 %0,%1;":"=f"(r):"f"(x)); return r; }
static __device__ __forceinline__ __half2 u2h(unsigned u){ return *reinterpret_cast<__half2*>(&u); }

// One block = 8 sequences (4 warps, 16 lanes per sequence).
// Phase 0: trans -> smem (raw fp32 + exp2-transposed fp16), cw/start -> smem.
// Phase 1: per-step m codes + gold transition/start partials (smem only).
// Phase 2: linear-domain CRF recursion. Rescale exponent comes from the fp16
//          bits of lane-0's p in the PS read; the power-of-2 is folded into the
//          per-step ex2 (exact integer addend) and logged in ksum.
__global__ __launch_bounds__(128)
void crf_fused(const float* __restrict__ em, const int* __restrict__ tags,
               const int* __restrict__ w2w, const int* __restrict__ icnt,
               const int* __restrict__ dist, const float* __restrict__ cw,
               const float* __restrict__ trans, const float* __restrict__ start,
               float* __restrict__ out)
{
    __shared__ __align__(16) __half ETT[4*384];     // exp2(trans*log2e)^T: [m][j][i], 48B j-stride
    __shared__ __align__(16) float TRR[1024];       // raw trans
    __shared__ float CW[16], ST[16];
    __shared__ __align__(16) unsigned CODES[8][64]; // 1 byte/step {m:2,t1:4,stash:2}
    __shared__ float GOLD[8];
    __shared__ __align__(16) __half PS[4][2][32];   // [warp][buf][lane]

    int tid = threadIdx.x;
    if (tid < 8) GOLD[tid] = 0.f;
    if (tid < 16) { CW[tid] = cw[tid]; ST[tid] = start[tid]; }
    #pragma unroll
    for (int k = 0; k < 8; ++k) {
        int idx = tid + k*128;                       // trans[m][i][jj]
        float v = trans[idx];
        TRR[idx] = v;
        int m = idx >> 8, i = (idx >> 4) & 15, jj = idx & 15;
        ETT[m*384 + jj*24 + i] = __float2half_rn(ex2f_(v * LOG2E));
    }
    __syncthreads();

    int seq0 = blockIdx.x*8;

    // ---- phase 1: codes + gold transition partials ----
    #pragma unroll 1
    for (int s2 = 0; s2 < 4; ++s2) {
        int s  = s2*2 + (tid >> 6);                  // 0..7
        int lt = tid & 63;
        int seq = seq0 + s;
        const int* tg = tags + seq*T_;
        int tb = lt*4;
        uint4 tg4 = *reinterpret_cast<const uint4*>(tg + tb);
        int tag4 = (lt < 63) ? tg[tb+4] : 0;
        int tc[5] = { (int)tg4.x, (int)tg4.y, (int)tg4.z, (int)tg4.w, tag4 };
        int base = seq*(T_-1) + tb;

        unsigned bytes = 0;
        float gsum = 0.f;
        #pragma unroll
        for (int k = 0; k < 4; ++k) {
            int t = tb + k;
            if (t < T_-1) {
                int a  = w2w [base+k];
                int ic = icnt[base+k];
                int di = dist[base+k];
                int m = (a==1) ? 0 : ((ic==0) ? 1 : ((di==0) ? 2 : 3));
                int t0 = tc[k], t1 = tc[k+1];
                gsum += CW[t1] * TRR[(m*16+t0)*16+t1];
                bytes |= ((unsigned)m | ((unsigned)t1 << 2)) << (k*8);
            } else {               // t == 255 slot: start-score gold part
                int s0 = __ldg(&tg[0]);
                gsum += CW[s0] * ST[s0];
            }
        }
        if (lt == 0) {             // stash tag[0] in spare bits of bytes 0,1
            bytes |= ((unsigned)tg4.x & 3u) << 6;
            bytes |= (((unsigned)tg4.x >> 2) & 3u) << 14;
        }
        CODES[s][lt] = bytes;

        gsum += __shfl_xor_sync(FULL, gsum, 16);
        gsum += __shfl_xor_sync(FULL, gsum, 8);
        gsum += __shfl_xor_sync(FULL, gsum, 4);
        gsum += __shfl_xor_sync(FULL, gsum, 2);
        gsum += __shfl_xor_sync(FULL, gsum, 1);
        if ((tid & 31) == 0) atomicAdd(&GOLD[s], gsum);
    }
    __syncthreads();

    // ---- phase 2: recursion ----
    int warp = tid >> 5, lane = tid & 31, h = lane >> 4, j = lane & 15;
    int s_loc = warp*2 + h;
    int seq = seq0 + s_loc;

    const float* pe = em + (size_t)seq*(T_*K_) + j;
    const uint2* pc = reinterpret_cast<const uint2*>(&CODES[s_loc][0]);
    const char* ettc = reinterpret_cast<const char*>(ETT);
    unsigned jrow = (unsigned)(j*48);

    float wj = CW[j];
    float sj = ST[j];
    float e0 = pe[0];

    uint2 cC = pc[0], cN = pc[1];
    int t0 = (int)((cC.x >> 6) & 3u) | ((int)((cC.x >> 14) & 3u) << 2);

    float pf0 = ex2f_((sj + e0) * LOG2E);
    float gold = (j == t0) ? wj * e0 : 0.f;

    // initial exact power-of-2 normalization (logged in ksum)
    float s0f = __shfl_sync(FULL, pf0, 0, 16);
    unsigned bi0 = __float_as_uint(s0f);
    int ksum = (int)(bi0 >> 23) - 121;
    pf0 *= __uint_as_float(0x7C000000u - (bi0 & 0x7f800000u));
    __half ph = __float2half_rn(pf0);

    float eb[8];
    #pragma unroll
    for (int r = 0; r < 8; ++r) eb[r] = pe[(r+1)*K_];

#define STEP(W, BY, SIDX, RI, BF) do {                                          \
    unsigned b_ = __byte_perm((W), 0u, 0x4440u | (unsigned)(BY));               \
    float e_ = eb[RI];                                                          \
    eb[RI] = pe[((SIDX)+9 < 255 ? (SIDX)+9 : 255)*K_];                          \
    PS[warp][BF][lane] = ph;                                                    \
    unsigned m_ = b_ & 3u;                                                      \
    const uint4* ev_ = reinterpret_cast<const uint4*>(ettc + m_*768u + jrow);   \
    uint4 E0_ = ev_[0], E1_ = ev_[1];                                           \
    const uint4* pv_ = reinterpret_cast<const uint4*>(&PS[warp][BF][h*16]);     \
    uint4 P0_ = pv_[0], P1_ = pv_[1];                                           \
    int k16_ = (int)((P0_.x >> 10) & 31u);                                      \
    ksum += k16_;                                                               \
    float eesc_ = ex2f_(fmaf(e_, LOG2E, (float)(9 - k16_)));                    \
    __half eh_ = __float2half_rn(eesc_);                                        \
    __half2 x_ = __hmul2(u2h(P0_.x), u2h(E0_.x));                               \
    __half2 y_ = __hmul2(u2h(P0_.y), u2h(E0_.y));                               \
    x_ = __hfma2(u2h(P0_.z), u2h(E0_.z), x_);                                   \
    y_ = __hfma2(u2h(P0_.w), u2h(E0_.w), y_);                                   \
    x_ = __hfma2(u2h(P1_.x), u2h(E1_.x), x_);                                   \
    y_ = __hfma2(u2h(P1_.y), u2h(E1_.y), y_);                                   \
    x_ = __hfma2(u2h(P1_.z), u2h(E1_.z), x_);                                   \
    y_ = __hfma2(u2h(P1_.w), u2h(E1_.w), y_);                                   \
    x_ = __hadd2(x_, y_);                                                       \
    __half hs_ = __hadd(__low2half(x_), __high2half(x_));                       \
    ph = __hmul(hs_, eh_);                                                      \
    if ((unsigned)j == ((b_ >> 2) & 15u)) gold = fmaf(wj, e_, gold);            \
} while (0)

    #pragma unroll 1
    for (int chunk = 0; chunk < 31; ++chunk) {
        int base = chunk*8;
        unsigned w0 = cC.x, w1 = cC.y;
        STEP(w0, 0, base+0, (base+0)&7, 0);
        STEP(w0, 1, base+1, (base+1)&7, 1);
        STEP(w0, 2, base+2, (base+2)&7, 0);
        STEP(w0, 3, base+3, (base+3)&7, 1);
        STEP(w1, 0, base+4, (base+4)&7, 0);
        STEP(w1, 1, base+5, (base+5)&7, 1);
        STEP(w1, 2, base+6, (base+6)&7, 0);
        STEP(w1, 3, base+7, (base+7)&7, 1);
        cC = cN; cN = pc[chunk+2 < 31 ? chunk+2 : 31];
    }
    // epilogue: steps 248..254 (slot-255 byte unused)
    {
        unsigned w0 = cC.x, w1 = cC.y;
        STEP(w0, 0, 248, 0, 0);
        STEP(w0, 1, 249, 1, 1);
        STEP(w0, 2, 250, 2, 0);
        STEP(w0, 3, 251, 3, 1);
        STEP(w1, 0, 252, 4, 0);
        STEP(w1, 1, 253, 5, 1);
        STEP(w1, 2, 254, 6, 0);
    }
#undef STEP

    // logZ = ln2 * (log2(sum_j p_j) + ksum - 9*255)
    float z = __half2float(ph);
    z += __shfl_xor_sync(FULL, z, 8, 16);
    z += __shfl_xor_sync(FULL, z, 4, 16);
    z += __shfl_xor_sync(FULL, z, 2, 16);
    z += __shfl_xor_sync(FULL, z, 1, 16);
    float logZ = LN2 * (lg2f_(z) + (float)(ksum - 9*255));

    float gg = gold;
    gg += __shfl_xor_sync(FULL, gg, 8, 16);
    gg += __shfl_xor_sync(FULL, gg, 4, 16);
    gg += __shfl_xor_sync(FULL, gg, 2, 16);
    gg += __shfl_xor_sync(FULL, gg, 1, 16);

    if (j == 0) {
        out[seq]      = gg + GOLD[s_loc];
        out[B_ + seq] = logZ;
    }
}

extern "C" void kernel_launch(void* const* d_in, const int* in_sizes, int n_in,
                              void* d_out, int out_size) {
    const float* em    = (const float*)d_in[0];
    const int*   tags  = (const int*)d_in[1];
    const int*   w2w   = (const int*)d_in[2];
    const int*   icnt  = (const int*)d_in[3];
    const int*   dist  = (const int*)d_in[4];
    const float* cw    = (const float*)d_in[5];
    const float* trans = (const float*)d_in[6];
    const float* start = (const float*)d_in[7];
    float* out = (float*)d_out;

    crf_fused<<<B_/8, 128>>>(em, tags, w2w, icnt, dist, cw, trans, start, out);
}